// round 1
// baseline (speedup 1.0000x reference)
#include <cuda_runtime.h>

// Fuzzy LeNet-5 (Yager p=1 == Lukasiewicz): every "conv" is a max-plus conv:
//   out = relu( max_{c,kh,kw}( x + w ) - 1 )
// relu commutes with the max-reductions, so conv+relu+maxpool2 fuses into a
// single max over (2x2 pool positions) x (receptive field), minus 1, relu'd.
// One CTA per image, everything staged through shared memory.

#define NTHREADS 256

__global__ __launch_bounds__(NTHREADS, 1)
void lenet_fuzzy_kernel(const float* __restrict__ g_in,   // [B,3,32,32]
                        const float* __restrict__ g_w1,   // [6,3,5,5]
                        const float* __restrict__ g_w2,   // [16,6,5,5]
                        const float* __restrict__ g_w3,   // [120,16,5,5]
                        const float* __restrict__ g_wd,   // [120,84]
                        const float* __restrict__ g_wf,   // [84,10]
                        const float* __restrict__ g_bf,   // [10]
                        float* __restrict__ g_out)        // [B,10]
{
    __shared__ __align__(16) float s_in[3 * 32 * 32];   // input image
    __shared__ float s_w1[6 * 75];                      // w1
    __shared__ float s_l1[6 * 14 * 14];                 // layer1 pooled out
    __shared__ float s_w2[16 * 150];                    // w2
    __shared__ __align__(16) float s_l2[400];           // layer2 pooled out (c*25+i*5+j)
    __shared__ float s_l3[120];                         // layer3 out
    __shared__ float s_h[84];                           // tanh hidden
    __shared__ float s_z[10];                           // logits
    __shared__ float s_ls;                              // logsumexp

    const int b   = blockIdx.x;
    const int tid = threadIdx.x;

    // ---- stage inputs & small weights into smem ----
    {
        const float4* img4 = reinterpret_cast<const float4*>(g_in + (size_t)b * 3072);
        float4* sin4 = reinterpret_cast<float4*>(s_in);
        #pragma unroll
        for (int i = tid; i < 768; i += NTHREADS) sin4[i] = img4[i];
        for (int i = tid; i < 450;  i += NTHREADS) s_w1[i] = g_w1[i];
        for (int i = tid; i < 2400; i += NTHREADS) s_w2[i] = g_w2[i];
    }
    __syncthreads();

    // ---- Layer 1: max-plus conv 5x5 (3->6) + relu + maxpool2 -> [6,14,14] ----
    for (int idx = tid; idx < 6 * 14 * 14; idx += NTHREADS) {
        const int o  = idx / 196;
        const int r  = idx - o * 196;
        const int ph = r / 14;
        const int pw = r - ph * 14;
        const int h0 = 2 * ph, w0 = 2 * pw;
        const float* wrow = s_w1 + o * 75;
        float a0 = 0.f, a1 = 0.f, a2 = 0.f, a3 = 0.f;  // terms x+w are >= 0
        for (int c = 0; c < 3; ++c) {
            #pragma unroll
            for (int kh = 0; kh < 5; ++kh) {
                const float* x0 = s_in + (c * 32 + h0 + kh) * 32 + w0;
                const float* x1 = x0 + 32;
                const float* wr = wrow + c * 25 + kh * 5;
                #pragma unroll
                for (int kw = 0; kw < 5; ++kw) {
                    const float wv = wr[kw];
                    a0 = fmaxf(a0, x0[kw]     + wv);
                    a1 = fmaxf(a1, x0[kw + 1] + wv);
                    a2 = fmaxf(a2, x1[kw]     + wv);
                    a3 = fmaxf(a3, x1[kw + 1] + wv);
                }
            }
        }
        const float m = fmaxf(fmaxf(a0, a1), fmaxf(a2, a3));
        s_l1[idx] = fmaxf(0.f, m - 1.f);
    }
    __syncthreads();

    // ---- Layer 2: max-plus conv 5x5 (6->16) + relu + maxpool2 -> [16,5,5] ----
    for (int idx = tid; idx < 400; idx += NTHREADS) {
        const int o  = idx / 25;
        const int r  = idx - o * 25;
        const int ph = r / 5;
        const int pw = r - ph * 5;
        const int h0 = 2 * ph, w0 = 2 * pw;
        const float* wrow = s_w2 + o * 150;
        float a0 = 0.f, a1 = 0.f, a2 = 0.f, a3 = 0.f;
        for (int c = 0; c < 6; ++c) {
            #pragma unroll
            for (int kh = 0; kh < 5; ++kh) {
                const float* x0 = s_l1 + (c * 14 + h0 + kh) * 14 + w0;
                const float* x1 = x0 + 14;
                const float* wr = wrow + c * 25 + kh * 5;
                #pragma unroll
                for (int kw = 0; kw < 5; ++kw) {
                    const float wv = wr[kw];
                    a0 = fmaxf(a0, x0[kw]     + wv);
                    a1 = fmaxf(a1, x0[kw + 1] + wv);
                    a2 = fmaxf(a2, x1[kw]     + wv);
                    a3 = fmaxf(a3, x1[kw + 1] + wv);
                }
            }
        }
        const float m = fmaxf(fmaxf(a0, a1), fmaxf(a2, a3));
        s_l2[idx] = fmaxf(0.f, m - 1.f);  // layout matches w3 patch order (c,kh,kw)
    }
    __syncthreads();

    // ---- Layer 3: max-plus "conv" 5x5 (16->120), output 1x1 -> [120] ----
    // warp-cooperative: each warp reduces full 400-term max for its outputs
    {
        const int warp = tid >> 5;
        const int lane = tid & 31;
        const float4* x4 = reinterpret_cast<const float4*>(s_l2);
        for (int o = warp; o < 120; o += (NTHREADS / 32)) {
            const float4* w4 = reinterpret_cast<const float4*>(g_w3 + (size_t)o * 400);
            float m = 0.f;
            #pragma unroll 2
            for (int j = lane; j < 100; j += 32) {
                const float4 wv = w4[j];
                const float4 xv = x4[j];
                m = fmaxf(m, xv.x + wv.x);
                m = fmaxf(m, xv.y + wv.y);
                m = fmaxf(m, xv.z + wv.z);
                m = fmaxf(m, xv.w + wv.w);
            }
            #pragma unroll
            for (int s = 16; s; s >>= 1)
                m = fmaxf(m, __shfl_xor_sync(0xffffffffu, m, s));
            if (lane == 0) s_l3[o] = fmaxf(0.f, m - 1.f);
        }
    }
    __syncthreads();

    // ---- DenseDefuzzy: h = tanh(l3 @ wd), wd [120,84] ----
    if (tid < 84) {
        float acc = 0.f;
        #pragma unroll 4
        for (int k = 0; k < 120; ++k)
            acc += s_l3[k] * g_wd[k * 84 + tid];   // coalesced across threads
        s_h[tid] = tanhf(acc);
    }
    __syncthreads();

    // ---- fc5: z = h @ wf + bf, wf [84,10] ----
    if (tid < 10) {
        float acc = g_bf[tid];
        #pragma unroll 4
        for (int j = 0; j < 84; ++j)
            acc += s_h[j] * g_wf[j * 10 + tid];
        s_z[tid] = acc;
    }
    __syncthreads();

    // ---- log_softmax ----
    if (tid == 0) {
        float m = s_z[0];
        #pragma unroll
        for (int i = 1; i < 10; ++i) m = fmaxf(m, s_z[i]);
        float s = 0.f;
        #pragma unroll
        for (int i = 0; i < 10; ++i) s += expf(s_z[i] - m);
        s_ls = m + logf(s);
    }
    __syncthreads();
    if (tid < 10) g_out[(size_t)b * 10 + tid] = s_z[tid] - s_ls;
}

extern "C" void kernel_launch(void* const* d_in, const int* in_sizes, int n_in,
                              void* d_out, int out_size)
{
    const float* inp = (const float*)d_in[0];
    const float* w1  = (const float*)d_in[1];
    const float* w2  = (const float*)d_in[2];
    const float* w3  = (const float*)d_in[3];
    const float* wd  = (const float*)d_in[4];
    const float* wf  = (const float*)d_in[5];
    const float* bf  = (const float*)d_in[6];
    float* out = (float*)d_out;

    const int B = in_sizes[0] / (3 * 32 * 32);
    lenet_fuzzy_kernel<<<B, NTHREADS>>>(inp, w1, w2, w3, wd, wf, bf, out);
}

// round 3
// speedup vs baseline: 1.1870x; 1.1870x over previous
#include <cuda_runtime.h>

// Fuzzy LeNet-5, Yager p=1 == Lukasiewicz t-norm:
//   conv_out = relu( max_{c,kh,kw}( x + w ) - 1 ),  relu commutes with maxpool,
// so conv+relu+maxpool2 fuses into one max over (2x2 pool) x (receptive field).
// One CTA per image, 512 threads. Inner loops register-staged:
//   - per input row: 3x float2 LDS (conflict-free across lanes, even offsets)
//   - weight row held in registers, rolling prev-row regs (each w loaded once)
//   - 4 independent max-accumulator chains (conv row x col parity)

#define NT 512

__device__ __forceinline__ void taps(float& a0, float& a1,
                                     float x0, float x1, float x2,
                                     float x3, float x4, float x5,
                                     float w0, float w1, float w2,
                                     float w3, float w4)
{
    a0 = fmaxf(a0, x0 + w0);  a1 = fmaxf(a1, x1 + w0);
    a0 = fmaxf(a0, x1 + w1);  a1 = fmaxf(a1, x2 + w1);
    a0 = fmaxf(a0, x2 + w2);  a1 = fmaxf(a1, x3 + w2);
    a0 = fmaxf(a0, x3 + w3);  a1 = fmaxf(a1, x4 + w3);
    a0 = fmaxf(a0, x4 + w4);  a1 = fmaxf(a1, x5 + w4);
}

// Max-plus conv 5x5 + relu + fused 2x2 maxpool for one pooled output.
// x: input base at (row 2*ph, col 2*pw) of this image/layer (even float index).
// w: 25-float kernel rows for this output channel, NC channels.
template<int NC, int CSTRIDE, int PITCH>
__device__ __forceinline__ float mp_cell(const float* __restrict__ x,
                                         const float* __restrict__ w)
{
    float aT0 = 0.f, aT1 = 0.f, aB0 = 0.f, aB1 = 0.f;  // terms x+w are >= 0
    #pragma unroll 1
    for (int c = 0; c < NC; ++c, x += CSTRIDE, w += 25) {
        float p0 = 0.f, p1 = 0.f, p2 = 0.f, p3 = 0.f, p4 = 0.f;
        #pragma unroll
        for (int ir = 0; ir < 6; ++ir) {
            const float* xp = x + ir * PITCH;
            const float2 A = *reinterpret_cast<const float2*>(xp);
            const float2 B = *reinterpret_cast<const float2*>(xp + 2);
            const float2 C = *reinterpret_cast<const float2*>(xp + 4);
            if (ir < 5) {
                const float* wr = w + ir * 5;
                const float q0 = wr[0], q1 = wr[1], q2 = wr[2],
                            q3 = wr[3], q4 = wr[4];
                // conv row r0 = 2ph uses kh = ir
                taps(aT0, aT1, A.x, A.y, B.x, B.y, C.x, C.y, q0, q1, q2, q3, q4);
                // conv row r1 = 2ph+1 uses kh = ir-1 (prev row's weights)
                if (ir >= 1)
                    taps(aB0, aB1, A.x, A.y, B.x, B.y, C.x, C.y, p0, p1, p2, p3, p4);
                p0 = q0; p1 = q1; p2 = q2; p3 = q3; p4 = q4;
            } else {
                taps(aB0, aB1, A.x, A.y, B.x, B.y, C.x, C.y, p0, p1, p2, p3, p4);
            }
        }
    }
    const float m = fmaxf(fmaxf(aT0, aB0), fmaxf(aT1, aB1));
    return fmaxf(0.f, m - 1.f);
}

__global__ __launch_bounds__(NT, 1)
void lenet_fuzzy_kernel(const float* __restrict__ g_in,   // [B,3,32,32]
                        const float* __restrict__ g_w1,   // [6,3,5,5]
                        const float* __restrict__ g_w2,   // [16,6,5,5]
                        const float* __restrict__ g_w3,   // [120,16,5,5]
                        const float* __restrict__ g_wd,   // [120,84]
                        const float* __restrict__ g_wf,   // [84,10]
                        const float* __restrict__ g_bf,   // [10]
                        float* __restrict__ g_out)        // [B,10]
{
    __shared__ __align__(16) float s_in[3 * 32 * 32];
    __shared__ __align__(8)  float s_w1[6 * 75];
    __shared__ __align__(8)  float s_l1[6 * 14 * 14];
    __shared__ __align__(8)  float s_w2[16 * 150];
    __shared__ __align__(16) float s_l2[400];
    __shared__ float s_l3[120];
    __shared__ float s_h[84];
    __shared__ float s_z[10];
    __shared__ float s_ls;

    const int b   = blockIdx.x;
    const int tid = threadIdx.x;

    // ---- stage image + small weights (scalar loads for w1/w2: unknown
    //      global alignment of those harness pointers) ----
    {
        const float4* img4 = reinterpret_cast<const float4*>(g_in + (size_t)b * 3072);
        float4* sin4 = reinterpret_cast<float4*>(s_in);
        #pragma unroll
        for (int i = tid; i < 768; i += NT) sin4[i] = img4[i];
        for (int i = tid; i < 450;  i += NT) s_w1[i] = g_w1[i];
        for (int i = tid; i < 2400; i += NT) s_w2[i] = g_w2[i];
    }
    __syncthreads();

    // ---- Layer 1: (3->6) conv5 + relu + pool2 -> [6,14,14] ----
    for (int idx = tid; idx < 6 * 14 * 14; idx += NT) {
        const int o  = idx / 196;
        const int r  = idx - o * 196;
        const int ph = r / 14;
        const int pw = r - ph * 14;
        const float* x = s_in + (2 * ph) * 32 + 2 * pw;
        s_l1[idx] = mp_cell<3, 1024, 32>(x, s_w1 + o * 75);
    }
    __syncthreads();

    // ---- Layer 2: (6->16) conv5 + relu + pool2 -> [16,5,5] ----
    for (int idx = tid; idx < 400; idx += NT) {
        const int o  = idx / 25;
        const int r  = idx - o * 25;
        const int ph = r / 5;
        const int pw = r - ph * 5;
        const float* x = s_l1 + (2 * ph) * 14 + 2 * pw;
        s_l2[idx] = mp_cell<6, 196, 14>(x, s_w2 + o * 150);  // layout = (c,kh,kw)
    }
    __syncthreads();

    // ---- Layer 3: (16->120) max-plus over all 400 features -> [120] ----
    {
        const int warp = tid >> 5;
        const int lane = tid & 31;
        const float4* x4 = reinterpret_cast<const float4*>(s_l2);
        for (int o = warp; o < 120; o += (NT / 32)) {
            const float4* w4 = reinterpret_cast<const float4*>(g_w3 + (size_t)o * 400);
            float m = 0.f;
            #pragma unroll 2
            for (int j = lane; j < 100; j += 32) {
                const float4 wv = w4[j];
                const float4 xv = x4[j];
                m = fmaxf(m, xv.x + wv.x);
                m = fmaxf(m, xv.y + wv.y);
                m = fmaxf(m, xv.z + wv.z);
                m = fmaxf(m, xv.w + wv.w);
            }
            #pragma unroll
            for (int s = 16; s; s >>= 1)
                m = fmaxf(m, __shfl_xor_sync(0xffffffffu, m, s));
            if (lane == 0) s_l3[o] = fmaxf(0.f, m - 1.f);
        }
    }
    __syncthreads();

    // ---- DenseDefuzzy: h = tanh(l3 @ wd), wd [120,84] ----
    if (tid < 84) {
        float acc = 0.f;
        #pragma unroll 4
        for (int k = 0; k < 120; ++k)
            acc += s_l3[k] * g_wd[k * 84 + tid];
        s_h[tid] = tanhf(acc);
    }
    __syncthreads();

    // ---- fc5: z = h @ wf + bf, wf [84,10] ----
    if (tid < 10) {
        float acc = g_bf[tid];
        #pragma unroll 4
        for (int j = 0; j < 84; ++j)
            acc += s_h[j] * g_wf[j * 10 + tid];
        s_z[tid] = acc;
    }
    __syncthreads();

    // ---- log_softmax ----
    if (tid == 0) {
        float m = s_z[0];
        #pragma unroll
        for (int i = 1; i < 10; ++i) m = fmaxf(m, s_z[i]);
        float s = 0.f;
        #pragma unroll
        for (int i = 0; i < 10; ++i) s += expf(s_z[i] - m);
        s_ls = m + logf(s);
    }
    __syncthreads();
    if (tid < 10) g_out[(size_t)b * 10 + tid] = s_z[tid] - s_ls;
}

extern "C" void kernel_launch(void* const* d_in, const int* in_sizes, int n_in,
                              void* d_out, int out_size)
{
    const float* inp = (const float*)d_in[0];
    const float* w1  = (const float*)d_in[1];
    const float* w2  = (const float*)d_in[2];
    const float* w3  = (const float*)d_in[3];
    const float* wd  = (const float*)d_in[4];
    const float* wf  = (const float*)d_in[5];
    const float* bf  = (const float*)d_in[6];
    float* out = (float*)d_out;

    const int B = in_sizes[0] / (3 * 32 * 32);
    lenet_fuzzy_kernel<<<B, NT>>>(inp, w1, w2, w3, wd, wf, bf, out);
}

// round 4
// speedup vs baseline: 1.6066x; 1.3535x over previous
#include <cuda_runtime.h>

// Fuzzy LeNet-5, Yager p=1 == Lukasiewicz:
//   conv_out = relu( max_{c,kh,kw}( x + w ) - 1 ); relu/maxpool fold into one max.
// One CTA per image, 512 threads, everything staged in (dynamic) shared memory.
// Head weights (w2, wd, wf, bf) arrive via cp.async overlapped with L1 compute.

#define NT 512

__device__ __forceinline__ unsigned smem_u32(const void* p) {
    return (unsigned)__cvta_generic_to_shared(p);
}
__device__ __forceinline__ void cp4(float* dst, const float* src) {
    asm volatile("cp.async.ca.shared.global [%0], [%1], 4;\n"
                 :: "r"(smem_u32(dst)), "l"(src));
}

__device__ __forceinline__ void taps(float& a0, float& a1,
                                     float x0, float x1, float x2,
                                     float x3, float x4, float x5,
                                     float w0, float w1, float w2,
                                     float w3, float w4)
{
    a0 = fmaxf(a0, x0 + w0);  a1 = fmaxf(a1, x1 + w0);
    a0 = fmaxf(a0, x1 + w1);  a1 = fmaxf(a1, x2 + w1);
    a0 = fmaxf(a0, x2 + w2);  a1 = fmaxf(a1, x3 + w2);
    a0 = fmaxf(a0, x3 + w3);  a1 = fmaxf(a1, x4 + w3);
    a0 = fmaxf(a0, x4 + w4);  a1 = fmaxf(a1, x5 + w4);
}

// Max-plus conv5x5 + relu + fused 2x2 maxpool for one pooled output.
template<int NC, int CSTRIDE, int PITCH>
__device__ __forceinline__ float mp_cell(const float* __restrict__ x,
                                         const float* __restrict__ w)
{
    float aT0 = 0.f, aT1 = 0.f, aB0 = 0.f, aB1 = 0.f;  // terms x+w >= 0
    #pragma unroll
    for (int c = 0; c < NC; ++c, x += CSTRIDE, w += 25) {
        float p0 = 0.f, p1 = 0.f, p2 = 0.f, p3 = 0.f, p4 = 0.f;
        #pragma unroll
        for (int ir = 0; ir < 6; ++ir) {
            const float* xp = x + ir * PITCH;
            const float2 A = *reinterpret_cast<const float2*>(xp);
            const float2 B = *reinterpret_cast<const float2*>(xp + 2);
            const float2 C = *reinterpret_cast<const float2*>(xp + 4);
            if (ir < 5) {
                const float* wr = w + ir * 5;
                const float q0 = wr[0], q1 = wr[1], q2 = wr[2],
                            q3 = wr[3], q4 = wr[4];
                taps(aT0, aT1, A.x, A.y, B.x, B.y, C.x, C.y, q0, q1, q2, q3, q4);
                if (ir >= 1)
                    taps(aB0, aB1, A.x, A.y, B.x, B.y, C.x, C.y, p0, p1, p2, p3, p4);
                p0 = q0; p1 = q1; p2 = q2; p3 = q3; p4 = q4;
            } else {
                taps(aB0, aB1, A.x, A.y, B.x, B.y, C.x, C.y, p0, p1, p2, p3, p4);
            }
        }
    }
    const float m = fmaxf(fmaxf(aT0, aB0), fmaxf(aT1, aB1));
    return fmaxf(0.f, m - 1.f);
}

// dynamic smem layout (floats)
#define OFF_IN  0        // 3072
#define OFF_W1  3072     // 450
#define OFF_L1  3522     // 1176  (even -> float2 ok)
#define OFF_W2  4698     // 2400
#define OFF_L2  7100     // 400   (16B aligned: 7100*4 % 16 == 0)
#define OFF_L3  7500     // 120
#define OFF_H   7620     // 84
#define OFF_WD  7704     // 10080
#define OFF_WF  17784    // 840
#define OFF_BF  18624    // 10
#define SMEM_FLOATS 18640

__global__ __launch_bounds__(NT, 1)
void lenet_fuzzy_kernel(const float* __restrict__ g_in,   // [B,3,32,32]
                        const float* __restrict__ g_w1,   // [6,3,5,5]
                        const float* __restrict__ g_w2,   // [16,6,5,5]
                        const float* __restrict__ g_w3,   // [120,16,5,5]
                        const float* __restrict__ g_wd,   // [120,84]
                        const float* __restrict__ g_wf,   // [84,10]
                        const float* __restrict__ g_bf,   // [10]
                        float* __restrict__ g_out)        // [B,10]
{
    extern __shared__ float sm[];
    float* s_in = sm + OFF_IN;
    float* s_w1 = sm + OFF_W1;
    float* s_l1 = sm + OFF_L1;
    float* s_w2 = sm + OFF_W2;
    float* s_l2 = sm + OFF_L2;
    float* s_l3 = sm + OFF_L3;
    float* s_h  = sm + OFF_H;
    float* s_wd = sm + OFF_WD;
    float* s_wf = sm + OFF_WF;
    float* s_bf = sm + OFF_BF;

    const int b    = blockIdx.x;
    const int tid  = threadIdx.x;
    const int warp = tid >> 5;
    const int lane = tid & 31;

    // ---- async staging: group0 = w2 (needed at L2), group1 = head weights ----
    for (int i = tid; i < 2400; i += NT) cp4(s_w2 + i, g_w2 + i);
    asm volatile("cp.async.commit_group;\n");
    for (int i = tid; i < 10080; i += NT) cp4(s_wd + i, g_wd + i);
    for (int i = tid; i < 840;   i += NT) cp4(s_wf + i, g_wf + i);
    if (tid < 10) cp4(s_bf + tid, g_bf + tid);
    asm volatile("cp.async.commit_group;\n");

    // ---- sync staging: image + w1 (needed now) ----
    {
        const float4* img4 = reinterpret_cast<const float4*>(g_in + (size_t)b * 3072);
        float4* sin4 = reinterpret_cast<float4*>(s_in);
        #pragma unroll
        for (int i = tid; i < 768; i += NT) sin4[i] = img4[i];
        for (int i = tid; i < 450; i += NT) s_w1[i] = g_w1[i];
    }
    __syncthreads();

    // ---- Layer 1: (3->6) conv5 + relu + pool2 -> [6,14,14] ----
    for (int idx = tid; idx < 6 * 14 * 14; idx += NT) {
        const int o  = idx / 196;
        const int r  = idx - o * 196;
        const int ph = r / 14;
        const int pw = r - ph * 14;
        const float* x = s_in + (2 * ph) * 32 + 2 * pw;
        s_l1[idx] = mp_cell<3, 1024, 32>(x, s_w1 + o * 75);
    }
    asm volatile("cp.async.wait_group 1;\n");   // w2 has landed
    __syncthreads();

    // ---- Layer 2: (6->16) conv5 + relu + pool2 -> [16,5,5] ----
    if (tid < 400) {
        const int o  = tid / 25;
        const int r  = tid - o * 25;
        const int ph = r / 5;
        const int pw = r - ph * 5;
        const float* x = s_l1 + (2 * ph) * 14 + 2 * pw;
        s_l2[tid] = mp_cell<6, 196, 14>(x, s_w2 + o * 150);  // layout = (c,kh,kw)
    }
    __syncthreads();

    // ---- Layer 3: (16->120) max-plus over 400 features -> [120] ----
    {
        const float4* x4 = reinterpret_cast<const float4*>(s_l2);
        for (int o = warp; o < 120; o += (NT / 32)) {
            const float4* w4 = reinterpret_cast<const float4*>(g_w3 + (size_t)o * 400);
            float m = 0.f;
            #pragma unroll 2
            for (int j = lane; j < 100; j += 32) {
                const float4 wv = w4[j];
                const float4 xv = x4[j];
                m = fmaxf(m, xv.x + wv.x);
                m = fmaxf(m, xv.y + wv.y);
                m = fmaxf(m, xv.z + wv.z);
                m = fmaxf(m, xv.w + wv.w);
            }
            #pragma unroll
            for (int s = 16; s; s >>= 1)
                m = fmaxf(m, __shfl_xor_sync(0xffffffffu, m, s));
            if (lane == 0) s_l3[o] = fmaxf(0.f, m - 1.f);
        }
    }
    asm volatile("cp.async.wait_group 0;\n");   // wd/wf/bf have landed
    __syncthreads();

    // ---- DenseDefuzzy: h = tanh(l3 @ wd), 4 threads per output ----
    {
        const int q = tid & 3;
        const int j = tid >> 2;           // 0..127
        const int jj = (j < 84) ? j : 83; // clamp so shfl lanes stay uniform
        float acc = 0.f;
        const int k0 = q * 30;
        #pragma unroll
        for (int k = 0; k < 30; ++k)
            acc += s_l3[k0 + k] * s_wd[(k0 + k) * 84 + jj];
        acc += __shfl_xor_sync(0xffffffffu, acc, 1);
        acc += __shfl_xor_sync(0xffffffffu, acc, 2);
        if (q == 0 && j < 84) s_h[j] = tanhf(acc);
    }
    __syncthreads();

    // ---- fc5 + log_softmax, entirely in warp 0 ----
    if (warp == 0) {
        const int l = (lane < 10) ? lane : 9;
        float acc = s_bf[l];
        #pragma unroll
        for (int j = 0; j < 84; ++j)
            acc += s_h[j] * s_wf[j * 10 + l];
        float v = (lane < 10) ? acc : -1e30f;
        #pragma unroll
        for (int s = 16; s; s >>= 1)
            v = fmaxf(v, __shfl_xor_sync(0xffffffffu, v, s));
        float e = (lane < 10) ? expf(acc - v) : 0.f;
        #pragma unroll
        for (int s = 16; s; s >>= 1)
            e += __shfl_xor_sync(0xffffffffu, e, s);
        const float ls = v + logf(e);
        if (lane < 10) g_out[(size_t)b * 10 + lane] = acc - ls;
    }
}

extern "C" void kernel_launch(void* const* d_in, const int* in_sizes, int n_in,
                              void* d_out, int out_size)
{
    const float* inp = (const float*)d_in[0];
    const float* w1  = (const float*)d_in[1];
    const float* w2  = (const float*)d_in[2];
    const float* w3  = (const float*)d_in[3];
    const float* wd  = (const float*)d_in[4];
    const float* wf  = (const float*)d_in[5];
    const float* bf  = (const float*)d_in[6];
    float* out = (float*)d_out;

    const int B = in_sizes[0] / (3 * 32 * 32);
    const int smem_bytes = SMEM_FLOATS * sizeof(float);
    cudaFuncSetAttribute(lenet_fuzzy_kernel,
                         cudaFuncAttributeMaxDynamicSharedMemorySize, smem_bytes);
    lenet_fuzzy_kernel<<<B, NT, smem_bytes>>>(inp, w1, w2, w3, wd, wf, bf, out);
}

// round 5
// speedup vs baseline: 1.6245x; 1.0111x over previous
#include <cuda_runtime.h>
#include <cstdint>

// Fuzzy LeNet-5, Yager p=1 == Lukasiewicz: conv_out = relu(max(x+w) - 1),
// relu/maxpool fold into one max over (2x2 pool)x(5x5 field).
// Conv layers run in s16 fixed point (scale 16383) using DPX
// __viaddmax_s16x2: one instruction = two max-plus terms (the two conv rows
// of a pooled cell live in the 16-bit lanes). add+max are exact in int.

#define NT 512
#define SCALE 16383.0f
#define ISCALE (1.0f / 16383.0f)
#define IONE 16383

__device__ __forceinline__ unsigned smem_u32(const void* p) {
    return (unsigned)__cvta_generic_to_shared(p);
}
__device__ __forceinline__ void cp4(float* dst, const float* src) {
    asm volatile("cp.async.ca.shared.global [%0], [%1], 4;\n"
                 :: "r"(smem_u32(dst)), "l"(src));
}

// 10 DPX ops: 5 taps x 2 column chains, both pool rows per op (s16x2 lanes).
__device__ __forceinline__ void taps_i16(uint32_t& a0, uint32_t& a1,
                                         const uint32_t* __restrict__ row,
                                         const uint32_t* __restrict__ wp)
{
    const uint2 A = *reinterpret_cast<const uint2*>(row);      // cols 0,1
    const uint2 B = *reinterpret_cast<const uint2*>(row + 2);  // cols 2,3
    const uint2 C = *reinterpret_cast<const uint2*>(row + 4);  // cols 4,5
    const uint32_t w0 = wp[0], w1 = wp[1], w2 = wp[2], w3 = wp[3], w4 = wp[4];
    a0 = __viaddmax_s16x2(A.x, w0, a0);  a1 = __viaddmax_s16x2(A.y, w0, a1);
    a0 = __viaddmax_s16x2(A.y, w1, a0);  a1 = __viaddmax_s16x2(B.x, w1, a1);
    a0 = __viaddmax_s16x2(B.x, w2, a0);  a1 = __viaddmax_s16x2(B.y, w2, a1);
    a0 = __viaddmax_s16x2(B.y, w3, a0);  a1 = __viaddmax_s16x2(C.x, w3, a1);
    a0 = __viaddmax_s16x2(C.x, w4, a0);  a1 = __viaddmax_s16x2(C.y, w4, a1);
}

// Pooled max-plus cell in s16x2. x points at packed pair-rows, base (2ph,2pw).
template<int NC, int CSTRIDE, int PITCH>
__device__ __forceinline__ int mp_cell_i16(const uint32_t* __restrict__ x,
                                           const uint32_t* __restrict__ w)
{
    uint32_t a0 = 0u, a1 = 0u;
    #pragma unroll
    for (int c = 0; c < NC; ++c) {
        #pragma unroll
        for (int kh = 0; kh < 5; ++kh)
            taps_i16(a0, a1, x + c * CSTRIDE + kh * PITCH, w + c * 25 + kh * 5);
    }
    const uint32_t cmb = __viaddmax_s16x2(a0, 0u, a1);  // lane-wise max
    const int lo = (int)(cmb & 0xFFFFu);                // values <= 32766 -> no sign issue
    const int hi = (int)(cmb >> 16);
    return max(lo, hi);
}

// dynamic smem layout (32-bit words)
#define OFF_IN   0       // 3072 f
#define OFF_W1P  3072    // 450 u32 (w,w)
#define OFF_P1   3522    // 2976 u32: [3][31][32] input pair-rows
#define OFF_P2   6498    // 1092 u32: [6][13][14] L1-out pair-rows
#define OFF_W2P  7590    // 2400 u32
#define OFF_L2F  9992    // 400 f (16B aligned)
#define OFF_L3   10392   // 120 f
#define OFF_H    10512   // 84 f
#define OFF_WD   10596   // 10080 f
#define OFF_WF   20676   // 840 f
#define OFF_BF   21516   // 10 f
#define SMEM_WORDS 21528

__global__ __launch_bounds__(NT, 1)
void lenet_fuzzy_kernel(const float* __restrict__ g_in,
                        const float* __restrict__ g_w1,
                        const float* __restrict__ g_w2,
                        const float* __restrict__ g_w3,
                        const float* __restrict__ g_wd,
                        const float* __restrict__ g_wf,
                        const float* __restrict__ g_bf,
                        float* __restrict__ g_out)
{
    extern __shared__ uint32_t sm[];
    float*    s_in  = reinterpret_cast<float*>(sm + OFF_IN);
    uint32_t* s_w1p = sm + OFF_W1P;
    uint32_t* s_p1  = sm + OFF_P1;
    uint32_t* s_p2  = sm + OFF_P2;
    uint32_t* s_w2p = sm + OFF_W2P;
    float*    s_l2f = reinterpret_cast<float*>(sm + OFF_L2F);
    float*    s_l3  = reinterpret_cast<float*>(sm + OFF_L3);
    float*    s_h   = reinterpret_cast<float*>(sm + OFF_H);
    float*    s_wd  = reinterpret_cast<float*>(sm + OFF_WD);
    float*    s_wf  = reinterpret_cast<float*>(sm + OFF_WF);
    float*    s_bf  = reinterpret_cast<float*>(sm + OFF_BF);

    const int b    = blockIdx.x;
    const int tid  = threadIdx.x;
    const int warp = tid >> 5;
    const int lane = tid & 31;

    // ---- async staging of head weights (consumed after L3) ----
    for (int i = tid; i < 10080; i += NT) cp4(s_wd + i, g_wd + i);
    for (int i = tid; i < 840;   i += NT) cp4(s_wf + i, g_wf + i);
    if (tid < 10) cp4(s_bf + tid, g_bf + tid);
    asm volatile("cp.async.commit_group;\n");

    // ---- stage image; quantize+pack w1, w2 straight from global ----
    {
        const float4* img4 = reinterpret_cast<const float4*>(g_in + (size_t)b * 3072);
        float4* sin4 = reinterpret_cast<float4*>(s_in);
        #pragma unroll
        for (int i = tid; i < 768; i += NT) sin4[i] = img4[i];
        for (int i = tid; i < 450; i += NT) {
            const int v = __float2int_rn(g_w1[i] * SCALE);
            s_w1p[i] = (uint32_t)(v | (v << 16));
        }
        for (int i = tid; i < 2400; i += NT) {
            const int v = __float2int_rn(g_w2[i] * SCALE);
            s_w2p[i] = (uint32_t)(v | (v << 16));
        }
    }
    __syncthreads();

    // ---- quantize input into pair-rows P1[c][i][col] = (row i, row i+1) ----
    for (int idx = tid; idx < 2976; idx += NT) {
        const int c   = idx / 992;           // 31*32
        const int rem = idx - c * 992;
        const float* p = s_in + c * 1024 + rem;
        const int v0 = __float2int_rn(p[0]  * SCALE);
        const int v1 = __float2int_rn(p[32] * SCALE);
        s_p1[idx] = (uint32_t)(v0 | (v1 << 16));
    }
    __syncthreads();

    // ---- Layer 1: (3->6) conv5+relu+pool2 -> s16 [6,14,14] into P2 pair-rows ----
    for (int idx = tid; idx < 6 * 14 * 14; idx += NT) {
        const int o  = idx / 196;
        const int r  = idx - o * 196;
        const int ph = r / 14;               // L1 output row (0..13)
        const int pw = r - ph * 14;          // L1 output col (0..13)
        const int m  = mp_cell_i16<3, 992, 32>(s_p1 + (2 * ph) * 32 + 2 * pw,
                                               s_w1p + o * 75);
        const uint16_t v = (uint16_t)max(m - IONE, 0);
        // P2[o][i][col]: lo = L1row i, hi = L1row i+1   (i in 0..12)
        uint16_t* p2h = reinterpret_cast<uint16_t*>(s_p2);
        if (ph <= 12) p2h[2 * (o * 182 + ph * 14 + pw)]           = v;  // lo of pair ph
        if (ph >= 1)  p2h[2 * (o * 182 + (ph - 1) * 14 + pw) + 1] = v;  // hi of pair ph-1
    }
    __syncthreads();

    // ---- Layer 2: (6->16) conv5+relu+pool2 -> float [16,5,5] ----
    if (tid < 400) {
        const int o  = tid / 25;
        const int r  = tid - o * 25;
        const int ph = r / 5;
        const int pw = r - ph * 5;
        const int m  = mp_cell_i16<6, 182, 14>(s_p2 + (2 * ph) * 14 + 2 * pw,
                                               s_w2p + o * 150);
        s_l2f[tid] = (float)max(m - IONE, 0) * ISCALE;  // order = (c,kh,kw)
    }
    __syncthreads();

    // ---- Layer 3: (16->120), 4 threads per output, 25 LDG.128 in flight ----
    if (tid < 480) {
        const int o = tid >> 2;
        const int q = tid & 3;
        const float4* w4 = reinterpret_cast<const float4*>(g_w3 + (size_t)o * 400 + q * 100);
        const float4* x4 = reinterpret_cast<const float4*>(s_l2f) + q * 25;
        float m = 0.f;
        #pragma unroll
        for (int k = 0; k < 25; ++k) {
            const float4 wv = w4[k];
            const float4 xv = x4[k];
            m = fmaxf(m, xv.x + wv.x);
            m = fmaxf(m, xv.y + wv.y);
            m = fmaxf(m, xv.z + wv.z);
            m = fmaxf(m, xv.w + wv.w);
        }
        m = fmaxf(m, __shfl_xor_sync(0xffffffffu, m, 1));
        m = fmaxf(m, __shfl_xor_sync(0xffffffffu, m, 2));
        if (q == 0) s_l3[o] = fmaxf(0.f, m - 1.f);
    }
    asm volatile("cp.async.wait_group 0;\n");
    __syncthreads();

    // ---- DenseDefuzzy: h = tanh(l3 @ wd), 4 threads per output ----
    {
        const int q  = tid & 3;
        const int j  = tid >> 2;
        const int jj = (j < 84) ? j : 83;
        float acc = 0.f;
        const int k0 = q * 30;
        #pragma unroll
        for (int k = 0; k < 30; ++k)
            acc += s_l3[k0 + k] * s_wd[(k0 + k) * 84 + jj];
        acc += __shfl_xor_sync(0xffffffffu, acc, 1);
        acc += __shfl_xor_sync(0xffffffffu, acc, 2);
        if (q == 0 && j < 84) s_h[j] = tanhf(acc);
    }
    __syncthreads();

    // ---- fc5 + log_softmax in warp 0 ----
    if (warp == 0) {
        const int l = (lane < 10) ? lane : 9;
        float acc = s_bf[l];
        #pragma unroll
        for (int j = 0; j < 84; ++j)
            acc += s_h[j] * s_wf[j * 10 + l];
        float v = (lane < 10) ? acc : -1e30f;
        #pragma unroll
        for (int s = 16; s; s >>= 1)
            v = fmaxf(v, __shfl_xor_sync(0xffffffffu, v, s));
        float e = (lane < 10) ? expf(acc - v) : 0.f;
        #pragma unroll
        for (int s = 16; s; s >>= 1)
            e += __shfl_xor_sync(0xffffffffu, e, s);
        const float ls = v + logf(e);
        if (lane < 10) g_out[(size_t)b * 10 + lane] = acc - ls;
    }
}

extern "C" void kernel_launch(void* const* d_in, const int* in_sizes, int n_in,
                              void* d_out, int out_size)
{
    const float* inp = (const float*)d_in[0];
    const float* w1  = (const float*)d_in[1];
    const float* w2  = (const float*)d_in[2];
    const float* w3  = (const float*)d_in[3];
    const float* wd  = (const float*)d_in[4];
    const float* wf  = (const float*)d_in[5];
    const float* bf  = (const float*)d_in[6];
    float* out = (float*)d_out;

    const int B = in_sizes[0] / (3 * 32 * 32);
    const int smem_bytes = SMEM_WORDS * 4;
    cudaFuncSetAttribute(lenet_fuzzy_kernel,
                         cudaFuncAttributeMaxDynamicSharedMemorySize, smem_bytes);
    lenet_fuzzy_kernel<<<B, NT, smem_bytes>>>(inp, w1, w2, w3, wd, wf, bf, out);
}

// round 8
// speedup vs baseline: 1.9763x; 1.2166x over previous
#include <cuda_runtime.h>
#include <cstdint>

// Fuzzy LeNet-5, Yager p=1 == Lukasiewicz: conv_out = relu(max(x+w) - 1);
// relu/maxpool fold into one max over (2x2 pool)x(5x5 field).
// Convs in s16 fixed point (scale 16383) with DPX __viaddmax_s16x2:
// one instruction = two max-plus terms (the two conv rows of a pooled cell
// live in the s16x2 lanes). Each thread computes a horizontal PAIR of pooled
// outputs -> 4 independent DPX chains, x-loads shared via LDS.128.

#define NT 640
#define SCALE 16383.0f
#define ISCALE (1.0f / 16383.0f)
#define IONE 16383

__device__ __forceinline__ unsigned smem_u32(const void* p) {
    return (unsigned)__cvta_generic_to_shared(p);
}
__device__ __forceinline__ void cp4(float* dst, const float* src) {
    asm volatile("cp.async.ca.shared.global [%0], [%1], 4;\n"
                 :: "r"(smem_u32(dst)), "l"(src));
}

// One weight row (5 taps) against 8 packed pair-columns -> updates 4 chains:
// A0/A1 = output pw (cols 0..5), B0/B1 = output pw+1 (cols 2..7).
__device__ __forceinline__ void taps_pair(uint32_t& A0, uint32_t& A1,
                                          uint32_t& B0, uint32_t& B1,
                                          const uint32_t* __restrict__ row,
                                          const uint32_t* __restrict__ wr)
{
    const uint4 Xa = *reinterpret_cast<const uint4*>(row);      // cols 0..3
    const uint4 Xb = *reinterpret_cast<const uint4*>(row + 4);  // cols 4..7
    const uint4 W  = *reinterpret_cast<const uint4*>(wr);       // w0..w3
    const uint32_t w4 = wr[4];
    A0 = __viaddmax_s16x2(Xa.x, W.x, A0);
    A1 = __viaddmax_s16x2(Xa.y, W.x, A1);
    B0 = __viaddmax_s16x2(Xa.z, W.x, B0);
    B1 = __viaddmax_s16x2(Xa.w, W.x, B1);
    A0 = __viaddmax_s16x2(Xa.y, W.y, A0);
    A1 = __viaddmax_s16x2(Xa.z, W.y, A1);
    B0 = __viaddmax_s16x2(Xa.w, W.y, B0);
    B1 = __viaddmax_s16x2(Xb.x, W.y, B1);
    A0 = __viaddmax_s16x2(Xa.z, W.z, A0);
    A1 = __viaddmax_s16x2(Xa.w, W.z, A1);
    B0 = __viaddmax_s16x2(Xb.x, W.z, B0);
    B1 = __viaddmax_s16x2(Xb.y, W.z, B1);
    A0 = __viaddmax_s16x2(Xa.w, W.w, A0);
    A1 = __viaddmax_s16x2(Xb.x, W.w, A1);
    B0 = __viaddmax_s16x2(Xb.y, W.w, B0);
    B1 = __viaddmax_s16x2(Xb.z, W.w, B1);
    A0 = __viaddmax_s16x2(Xb.x, w4, A0);
    A1 = __viaddmax_s16x2(Xb.y, w4, A1);
    B0 = __viaddmax_s16x2(Xb.z, w4, B0);
    B1 = __viaddmax_s16x2(Xb.w, w4, B1);
}

// Pooled max-plus pair of cells. x: packed pair-rows at base (2ph, 4pwp),
// 16B-aligned. w: padded weight rows, stride 8 per (c,kh).
template<int NC, int CSTRIDE, int PITCH>
__device__ __forceinline__ void mp_pair(const uint32_t* __restrict__ x,
                                        const uint32_t* __restrict__ w,
                                        int& m0, int& m1)
{
    uint32_t A0 = 0u, A1 = 0u, B0 = 0u, B1 = 0u;
    #pragma unroll
    for (int c = 0; c < NC; ++c) {
        #pragma unroll
        for (int kh = 0; kh < 5; ++kh)
            taps_pair(A0, A1, B0, B1,
                      x + c * CSTRIDE + kh * PITCH, w + (c * 5 + kh) * 8);
    }
    const uint32_t ca = __viaddmax_s16x2(A0, 0u, A1);
    const uint32_t cb = __viaddmax_s16x2(B0, 0u, B1);
    m0 = max((int)(ca & 0xFFFFu), (int)(ca >> 16));   // values <= 32766
    m1 = max((int)(cb & 0xFFFFu), (int)(cb >> 16));
}

// dynamic smem layout (32-bit words)
#define OFF_IN   0       // 3072 f
#define OFF_W1P  3072    // 720 u32: [6][3][5][8] padded (w,w)
#define OFF_P1   3792    // 2976 u32: [3][31][32] input pair-rows
#define OFF_P2   6768    // 1248 u32: [6][13][16] L1-out pair-rows (padded)
#define OFF_W2P  8016    // 3840 u32: [16][6][5][8]
#define OFF_L2F  11856   // 400 f (16B aligned)
#define OFF_L3   12256   // 120 f
#define OFF_H    12376   // 84 f
#define OFF_WD   12460   // 10080 f
#define OFF_WF   22540   // 840 f
#define OFF_BF   23380   // 10 f
#define SMEM_WORDS 23390

__global__ __launch_bounds__(NT, 1)
void lenet_fuzzy_kernel(const float* __restrict__ g_in,
                        const float* __restrict__ g_w1,
                        const float* __restrict__ g_w2,
                        const float* __restrict__ g_w3,
                        const float* __restrict__ g_wd,
                        const float* __restrict__ g_wf,
                        const float* __restrict__ g_bf,
                        float* __restrict__ g_out)
{
    extern __shared__ uint32_t sm[];
    float*    s_in  = reinterpret_cast<float*>(sm + OFF_IN);
    uint32_t* s_w1p = sm + OFF_W1P;
    uint32_t* s_p1  = sm + OFF_P1;
    uint32_t* s_p2  = sm + OFF_P2;
    uint32_t* s_w2p = sm + OFF_W2P;
    float*    s_l2f = reinterpret_cast<float*>(sm + OFF_L2F);
    float*    s_l3  = reinterpret_cast<float*>(sm + OFF_L3);
    float*    s_h   = reinterpret_cast<float*>(sm + OFF_H);
    float*    s_wd  = reinterpret_cast<float*>(sm + OFF_WD);
    float*    s_wf  = reinterpret_cast<float*>(sm + OFF_WF);
    float*    s_bf  = reinterpret_cast<float*>(sm + OFF_BF);

    const int b    = blockIdx.x;
    const int tid  = threadIdx.x;
    const int warp = tid >> 5;
    const int lane = tid & 31;

    // ---- async staging of head weights (consumed after L3) ----
    for (int i = tid; i < 10080; i += NT) cp4(s_wd + i, g_wd + i);
    for (int i = tid; i < 840;   i += NT) cp4(s_wf + i, g_wf + i);
    if (tid < 10) cp4(s_bf + tid, g_bf + tid);
    asm volatile("cp.async.commit_group;\n");

    // ---- stage image; quantize+pack conv weights (padded stride-8 rows);
    //      zero P2 pad columns (cols 14,15 of each pair-row) ----
    {
        const float4* img4 = reinterpret_cast<const float4*>(g_in + (size_t)b * 3072);
        float4* sin4 = reinterpret_cast<float4*>(s_in);
        #pragma unroll
        for (int i = tid; i < 768; i += NT) sin4[i] = img4[i];
        for (int i = tid; i < 450; i += NT) {
            const int o = i / 75, r = i - o * 75;      // r = c*25 + kh*5 + kw
            const int rk = r / 5, kw = r - rk * 5;     // rk = c*5 + kh
            const int v = __float2int_rn(g_w1[i] * SCALE);
            s_w1p[o * 120 + rk * 8 + kw] = (uint32_t)(v | (v << 16));
        }
        for (int i = tid; i < 2400; i += NT) {
            const int o = i / 150, r = i - o * 150;
            const int rk = r / 5, kw = r - rk * 5;
            const int v = __float2int_rn(g_w2[i] * SCALE);
            s_w2p[o * 240 + rk * 8 + kw] = (uint32_t)(v | (v << 16));
        }
        // P2 padding: 6*13 pair-rows, cols 14,15 (only read by discarded
        // B-chains of the cg=2 pair in L2; zero them for determinism)
        for (int i = tid; i < 78; i += NT) {
            s_p2[i * 16 + 14] = 0u;
            s_p2[i * 16 + 15] = 0u;
        }
    }
    __syncthreads();

    // ---- quantize input into pair-rows P1[c][i][col] = (row i, row i+1) ----
    for (int idx = tid; idx < 2976; idx += NT) {
        const int c   = idx / 992;           // 31*32
        const int rem = idx - c * 992;
        const float* p = s_in + c * 1024 + rem;
        const int v0 = __float2int_rn(p[0]  * SCALE);
        const int v1 = __float2int_rn(p[32] * SCALE);
        s_p1[idx] = (uint32_t)(v0 | (v1 << 16));
    }
    __syncthreads();

    // ---- Layer 1: (3->6) conv5+relu+pool2, one output-PAIR per thread ----
    if (tid < 588) {                          // 6 ch * 14 rows * 7 pairs
        const int o   = tid / 98;
        const int rem = tid - o * 98;
        const int ph  = rem / 7;              // out row 0..13
        const int pwp = rem - ph * 7;         // pair 0..6 -> cols 2pwp, 2pwp+1
        int m0, m1;
        mp_pair<3, 992, 32>(s_p1 + (2 * ph) * 32 + 4 * pwp, s_w1p + o * 120, m0, m1);
        const uint16_t v0 = (uint16_t)max(m0 - IONE, 0);
        const uint16_t v1 = (uint16_t)max(m1 - IONE, 0);
        uint16_t* p2h = reinterpret_cast<uint16_t*>(s_p2);
        const int pw0 = 2 * pwp;
        // P2[o][i][col]: lo = L1 row i, hi = L1 row i+1  (i in 0..12, stride 16)
        if (ph <= 12) {
            p2h[2 * (o * 208 + ph * 16 + pw0)]           = v0;
            p2h[2 * (o * 208 + ph * 16 + pw0 + 1)]       = v1;
        }
        if (ph >= 1) {
            p2h[2 * (o * 208 + (ph - 1) * 16 + pw0) + 1]     = v0;
            p2h[2 * (o * 208 + (ph - 1) * 16 + pw0 + 1) + 1] = v1;
        }
    }
    __syncthreads();

    // ---- Layer 2: (6->16) conv5+relu+pool2, 2 threads per output-pair
    //      (3 input channels each), shfl-combined ----
    if (tid < 480) {                          // 16 o * 5 ph * 3 colgroups * 2
        const int half = tid & 1;
        const int pi   = tid >> 1;            // 0..239
        const int o    = pi / 15;
        const int rem  = pi - o * 15;
        const int ph   = rem / 3;             // out row 0..4
        const int cg   = rem - ph * 3;        // colgroup: pw = 2cg, 2cg+1 (cg2: pw 4 only)
        int m0, m1;
        mp_pair<3, 208, 16>(s_p2 + (half * 3) * 208 + (2 * ph) * 16 + 4 * cg,
                            s_w2p + o * 240 + half * 120, m0, m1);
        m0 = max(m0, __shfl_xor_sync(0xffffffffu, m0, 1));
        m1 = max(m1, __shfl_xor_sync(0xffffffffu, m1, 1));
        if (half == 0) {
            const int base = o * 25 + ph * 5 + 2 * cg;
            s_l2f[base] = (float)max(m0 - IONE, 0) * ISCALE;
            if (cg < 2) s_l2f[base + 1] = (float)max(m1 - IONE, 0) * ISCALE;
        }
    }
    __syncthreads();

    // ---- Layer 3: (16->120), 4 threads per output, 25 LDG.128 in flight ----
    if (tid < 480) {
        const int o = tid >> 2;
        const int q = tid & 3;
        const float4* w4 = reinterpret_cast<const float4*>(g_w3 + (size_t)o * 400 + q * 100);
        const float4* x4 = reinterpret_cast<const float4*>(s_l2f) + q * 25;
        float m = 0.f;
        #pragma unroll
        for (int k = 0; k < 25; ++k) {
            const float4 wv = w4[k];
            const float4 xv = x4[k];
            m = fmaxf(m, xv.x + wv.x);
            m = fmaxf(m, xv.y + wv.y);
            m = fmaxf(m, xv.z + wv.z);
            m = fmaxf(m, xv.w + wv.w);
        }
        m = fmaxf(m, __shfl_xor_sync(0xffffffffu, m, 1));
        m = fmaxf(m, __shfl_xor_sync(0xffffffffu, m, 2));
        if (q == 0) s_l3[o] = fmaxf(0.f, m - 1.f);
    }
    asm volatile("cp.async.wait_group 0;\n");
    __syncthreads();

    // ---- DenseDefuzzy: h = tanh(l3 @ wd), 4 threads per output ----
    {
        const int q  = tid & 3;
        const int j  = tid >> 2;
        const int jj = (j < 84) ? j : 83;
        float acc = 0.f;
        const int k0 = q * 30;
        #pragma unroll
        for (int k = 0; k < 30; ++k)
            acc += s_l3[k0 + k] * s_wd[(k0 + k) * 84 + jj];
        acc += __shfl_xor_sync(0xffffffffu, acc, 1);
        acc += __shfl_xor_sync(0xffffffffu, acc, 2);
        if (q == 0 && j < 84) s_h[j] = tanhf(acc);
    }
    __syncthreads();

    // ---- fc5 + log_softmax in warp 0 ----
    if (warp == 0) {
        const int l = (lane < 10) ? lane : 9;
        float acc = s_bf[l];
        #pragma unroll
        for (int j = 0; j < 84; ++j)
            acc += s_h[j] * s_wf[j * 10 + l];
        float v = (lane < 10) ? acc : -1e30f;
        #pragma unroll
        for (int s = 16; s; s >>= 1)
            v = fmaxf(v, __shfl_xor_sync(0xffffffffu, v, s));
        float e = (lane < 10) ? expf(acc - v) : 0.f;
        #pragma unroll
        for (int s = 16; s; s >>= 1)
            e += __shfl_xor_sync(0xffffffffu, e, s);
        const float ls = v + logf(e);
        if (lane < 10) g_out[(size_t)b * 10 + lane] = acc - ls;
    }
}

extern "C" void kernel_launch(void* const* d_in, const int* in_sizes, int n_in,
                              void* d_out, int out_size)
{
    const float* inp = (const float*)d_in[0];
    const float* w1  = (const float*)d_in[1];
    const float* w2  = (const float*)d_in[2];
    const float* w3  = (const float*)d_in[3];
    const float* wd  = (const float*)d_in[4];
    const float* wf  = (const float*)d_in[5];
    const float* bf  = (const float*)d_in[6];
    float* out = (float*)d_out;

    const int B = in_sizes[0] / (3 * 32 * 32);
    const int smem_bytes = SMEM_WORDS * 4;
    cudaFuncSetAttribute(lenet_fuzzy_kernel,
                         cudaFuncAttributeMaxDynamicSharedMemorySize, smem_bytes);
    lenet_fuzzy_kernel<<<B, NT, smem_bytes>>>(inp, w1, w2, w3, wd, wf, bf, out);
}